// round 1
// baseline (speedup 1.0000x reference)
#include <cuda_runtime.h>
#include <cstdint>

// Problem shape (fixed by the dataset)
#define B 16
#define Q 20000
#define C 80
#define K 100

// Scratch (no cudaMalloc allowed)
__device__ unsigned int g_keys[B * Q];   // monotone-mapped max-logit per row
__device__ int          g_topk[B * K];   // selected indices, sorted per JAX topk order

// float -> uint monotone map (bigger float => bigger uint)
__device__ __forceinline__ unsigned int f2u(float f) {
    unsigned int u = __float_as_uint(f);
    return (u & 0x80000000u) ? ~u : (u | 0x80000000u);
}

// ---------------------------------------------------------------------------
// Kernel 1: per-row max over C=80 logits. One warp per row, coalesced.
// ---------------------------------------------------------------------------
__global__ void score_kernel(const float* __restrict__ logits) {
    int warp_id = (blockIdx.x * blockDim.x + threadIdx.x) >> 5;
    int lane = threadIdx.x & 31;
    if (warp_id >= B * Q) return;

    const float* row = logits + (long long)warp_id * C;
    float m = -3.4e38f;
    // lanes 0..31 read c, c+32; lanes 0..15 read c+64  (C=80)
    m = fmaxf(m, row[lane]);
    m = fmaxf(m, row[lane + 32]);
    if (lane < 16) m = fmaxf(m, row[lane + 64]);

    #pragma unroll
    for (int off = 16; off > 0; off >>= 1)
        m = fmaxf(m, __shfl_xor_sync(0xffffffffu, m, off));

    if (lane == 0) g_keys[warp_id] = f2u(m);
}

// ---------------------------------------------------------------------------
// Kernel 2: per-batch exact top-K select (radix-select + bitonic sort).
// One block per batch, 256 threads.
// ---------------------------------------------------------------------------
__global__ void topk_kernel() {
    const int b = blockIdx.x;
    const int tid = threadIdx.x;
    const unsigned int* keys = g_keys + b * Q;

    __shared__ int hist[256];
    __shared__ unsigned int s_prefix;
    __shared__ int s_krem;
    __shared__ unsigned long long cand[256];
    __shared__ int s_cnt;

    if (tid == 0) { s_prefix = 0u; s_krem = K; }
    __syncthreads();

    // 4 MSB-first radix passes to find the exact K-th largest key
    for (int pass = 0; pass < 4; ++pass) {
        int shift = 24 - 8 * pass;
        unsigned int decided_mask = (pass == 0) ? 0u : (0xFFFFFFFFu << (shift + 8));
        unsigned int prefix = s_prefix;

        if (tid < 256) hist[tid] = 0;
        __syncthreads();

        for (int i = tid; i < Q; i += blockDim.x) {
            unsigned int kk = keys[i];
            if ((kk & decided_mask) == prefix)
                atomicAdd(&hist[(kk >> shift) & 255u], 1);
        }
        __syncthreads();

        if (tid == 0) {
            int krem = s_krem;
            int d = 255;
            for (; d >= 0; --d) {
                int c = hist[d];
                if (c >= krem) break;
                krem -= c;
            }
            if (d < 0) d = 0;  // defensive; cannot happen
            s_prefix = prefix | ((unsigned int)d << shift);
            s_krem = krem;
        }
        __syncthreads();
    }

    unsigned int T = s_prefix;  // exact K-th largest key

    // Gather all candidates with key >= T (count in [K, K + dup(T) - 1])
    if (tid == 0) s_cnt = 0;
    __syncthreads();
    for (int i = tid; i < Q; i += blockDim.x) {
        unsigned int kk = keys[i];
        if (kk >= T) {
            int pos = atomicAdd(&s_cnt, 1);
            if (pos < 256)
                cand[pos] = ((unsigned long long)kk << 32) |
                            (unsigned long long)(0xFFFFFFFFu - (unsigned int)i);
        }
    }
    __syncthreads();
    int n = s_cnt < 256 ? s_cnt : 256;
    // pad
    if (tid >= n && tid < 256) cand[tid] = 0ull;
    __syncthreads();

    // Bitonic sort 256 composites DESCENDING:
    //   key desc; equal keys -> (0xFFFFFFFF - idx) desc == idx asc  (matches JAX stable topk)
    for (int kk = 2; kk <= 256; kk <<= 1) {
        for (int j = kk >> 1; j > 0; j >>= 1) {
            int i = tid;
            int ixj = i ^ j;
            if (ixj > i) {
                unsigned long long a = cand[i], bb = cand[ixj];
                bool up = ((i & kk) == 0);   // descending in "up" segments
                if ((a < bb) == up) { cand[i] = bb; cand[ixj] = a; }
            }
            __syncthreads();
        }
    }

    if (tid < K) {
        unsigned int enc = (unsigned int)(cand[tid] & 0xFFFFFFFFull);
        g_topk[b * K + tid] = (int)(0xFFFFFFFFu - enc);
    }
}

// ---------------------------------------------------------------------------
// Kernel 3: gather boxes + sigmoid(logits). One warp per detection.
// Output layout: [B*K*4 boxes][B*K*C scores], both f32.
// ---------------------------------------------------------------------------
__global__ void gather_kernel(const float* __restrict__ boxes,
                              const float* __restrict__ logits,
                              float* __restrict__ out) {
    int warp_id = (blockIdx.x * blockDim.x + threadIdx.x) >> 5;
    int lane = threadIdx.x & 31;
    if (warp_id >= B * K) return;

    int b = warp_id / K;
    int j = warp_id % K;
    int idx = g_topk[warp_id];

    const float* lrow = logits + ((long long)b * Q + idx) * C;
    float* srow = out + (long long)B * K * 4 + (long long)warp_id * C;

    // C = 80: lanes do c, c+32, (c+64 for lane<16)
    float x0 = lrow[lane];
    float x1 = lrow[lane + 32];
    srow[lane]      = 1.f / (1.f + __expf(-x0));
    srow[lane + 32] = 1.f / (1.f + __expf(-x1));
    if (lane < 16) {
        float x2 = lrow[lane + 64];
        srow[lane + 64] = 1.f / (1.f + __expf(-x2));
    }

    if (lane < 4) {
        out[(long long)warp_id * 4 + lane] = boxes[((long long)b * Q + idx) * 4 + lane];
    }
    (void)j;
}

// ---------------------------------------------------------------------------
extern "C" void kernel_launch(void* const* d_in, const int* in_sizes, int n_in,
                              void* d_out, int out_size) {
    const float* boxes  = (const float*)d_in[0];   // (B,Q,4)
    const float* logits = (const float*)d_in[1];   // (B,Q,C)
    float* out = (float*)d_out;

    // Kernel 1: one warp per row, 8 warps/block
    {
        int rows = B * Q;
        int warps_per_block = 8;
        int blocks = (rows + warps_per_block - 1) / warps_per_block;
        score_kernel<<<blocks, warps_per_block * 32>>>(logits);
    }
    // Kernel 2: one block per batch
    topk_kernel<<<B, 256>>>();
    // Kernel 3: one warp per detection
    {
        int dets = B * K;
        int warps_per_block = 8;
        int blocks = (dets + warps_per_block - 1) / warps_per_block;
        gather_kernel<<<blocks, warps_per_block * 32>>>(boxes, logits, out);
    }
    (void)in_sizes; (void)n_in; (void)out_size;
}

// round 2
// speedup vs baseline: 1.0059x; 1.0059x over previous
#include <cuda_runtime.h>
#include <cstdint>

// Problem shape (fixed by the dataset)
#define B 16
#define Q 20000
#define C 80
#define K 100

// Scratch (no cudaMalloc allowed)
__device__ unsigned int g_keys[B * Q];   // monotone-mapped max-logit per row
__device__ int          g_topk[B * K];   // selected indices, sorted per JAX topk order

// float -> uint monotone map (bigger float => bigger uint)
__device__ __forceinline__ unsigned int f2u(float f) {
    unsigned int u = __float_as_uint(f);
    return (u & 0x80000000u) ? ~u : (u | 0x80000000u);
}

// ---------------------------------------------------------------------------
// Kernel 1: per-row max over C=80 logits. One warp per row, coalesced.
// ---------------------------------------------------------------------------
__global__ void score_kernel(const float* __restrict__ logits) {
    int warp_id = (blockIdx.x * blockDim.x + threadIdx.x) >> 5;
    int lane = threadIdx.x & 31;
    if (warp_id >= B * Q) return;

    const float* row = logits + (long long)warp_id * C;
    float m = -3.4e38f;
    // lanes 0..31 read c, c+32; lanes 0..15 read c+64  (C=80)
    m = fmaxf(m, row[lane]);
    m = fmaxf(m, row[lane + 32]);
    if (lane < 16) m = fmaxf(m, row[lane + 64]);

    #pragma unroll
    for (int off = 16; off > 0; off >>= 1)
        m = fmaxf(m, __shfl_xor_sync(0xffffffffu, m, off));

    if (lane == 0) g_keys[warp_id] = f2u(m);
}

// ---------------------------------------------------------------------------
// Kernel 2: per-batch exact top-K select (radix-select + bitonic sort).
// One block per batch, 256 threads.
// ---------------------------------------------------------------------------
__global__ void topk_kernel() {
    const int b = blockIdx.x;
    const int tid = threadIdx.x;
    const unsigned int* keys = g_keys + b * Q;

    __shared__ int hist[256];
    __shared__ unsigned int s_prefix;
    __shared__ int s_krem;
    __shared__ unsigned long long cand[256];
    __shared__ int s_cnt;

    if (tid == 0) { s_prefix = 0u; s_krem = K; }
    __syncthreads();

    // 4 MSB-first radix passes to find the exact K-th largest key
    for (int pass = 0; pass < 4; ++pass) {
        int shift = 24 - 8 * pass;
        unsigned int decided_mask = (pass == 0) ? 0u : (0xFFFFFFFFu << (shift + 8));
        unsigned int prefix = s_prefix;

        if (tid < 256) hist[tid] = 0;
        __syncthreads();

        for (int i = tid; i < Q; i += blockDim.x) {
            unsigned int kk = keys[i];
            if ((kk & decided_mask) == prefix)
                atomicAdd(&hist[(kk >> shift) & 255u], 1);
        }
        __syncthreads();

        if (tid == 0) {
            int krem = s_krem;
            int d = 255;
            for (; d >= 0; --d) {
                int c = hist[d];
                if (c >= krem) break;
                krem -= c;
            }
            if (d < 0) d = 0;  // defensive; cannot happen
            s_prefix = prefix | ((unsigned int)d << shift);
            s_krem = krem;
        }
        __syncthreads();
    }

    unsigned int T = s_prefix;  // exact K-th largest key

    // Gather all candidates with key >= T (count in [K, K + dup(T) - 1])
    if (tid == 0) s_cnt = 0;
    __syncthreads();
    for (int i = tid; i < Q; i += blockDim.x) {
        unsigned int kk = keys[i];
        if (kk >= T) {
            int pos = atomicAdd(&s_cnt, 1);
            if (pos < 256)
                cand[pos] = ((unsigned long long)kk << 32) |
                            (unsigned long long)(0xFFFFFFFFu - (unsigned int)i);
        }
    }
    __syncthreads();
    int n = s_cnt < 256 ? s_cnt : 256;
    // pad
    if (tid >= n && tid < 256) cand[tid] = 0ull;
    __syncthreads();

    // Bitonic sort 256 composites DESCENDING:
    //   key desc; equal keys -> (0xFFFFFFFF - idx) desc == idx asc  (matches JAX stable topk)
    for (int kk = 2; kk <= 256; kk <<= 1) {
        for (int j = kk >> 1; j > 0; j >>= 1) {
            int i = tid;
            int ixj = i ^ j;
            if (ixj > i) {
                unsigned long long a = cand[i], bb = cand[ixj];
                bool up = ((i & kk) == 0);   // descending in "up" segments
                if ((a < bb) == up) { cand[i] = bb; cand[ixj] = a; }
            }
            __syncthreads();
        }
    }

    if (tid < K) {
        unsigned int enc = (unsigned int)(cand[tid] & 0xFFFFFFFFull);
        g_topk[b * K + tid] = (int)(0xFFFFFFFFu - enc);
    }
}

// ---------------------------------------------------------------------------
// Kernel 3: gather boxes + sigmoid(logits). One warp per detection.
// Output layout: [B*K*4 boxes][B*K*C scores], both f32.
// ---------------------------------------------------------------------------
__global__ void gather_kernel(const float* __restrict__ boxes,
                              const float* __restrict__ logits,
                              float* __restrict__ out) {
    int warp_id = (blockIdx.x * blockDim.x + threadIdx.x) >> 5;
    int lane = threadIdx.x & 31;
    if (warp_id >= B * K) return;

    int b = warp_id / K;
    int j = warp_id % K;
    int idx = g_topk[warp_id];

    const float* lrow = logits + ((long long)b * Q + idx) * C;
    float* srow = out + (long long)B * K * 4 + (long long)warp_id * C;

    // C = 80: lanes do c, c+32, (c+64 for lane<16)
    float x0 = lrow[lane];
    float x1 = lrow[lane + 32];
    srow[lane]      = 1.f / (1.f + __expf(-x0));
    srow[lane + 32] = 1.f / (1.f + __expf(-x1));
    if (lane < 16) {
        float x2 = lrow[lane + 64];
        srow[lane + 64] = 1.f / (1.f + __expf(-x2));
    }

    if (lane < 4) {
        out[(long long)warp_id * 4 + lane] = boxes[((long long)b * Q + idx) * 4 + lane];
    }
    (void)j;
}

// ---------------------------------------------------------------------------
extern "C" void kernel_launch(void* const* d_in, const int* in_sizes, int n_in,
                              void* d_out, int out_size) {
    const float* boxes  = (const float*)d_in[0];   // (B,Q,4)
    const float* logits = (const float*)d_in[1];   // (B,Q,C)
    float* out = (float*)d_out;

    // Kernel 1: one warp per row, 8 warps/block
    {
        int rows = B * Q;
        int warps_per_block = 8;
        int blocks = (rows + warps_per_block - 1) / warps_per_block;
        score_kernel<<<blocks, warps_per_block * 32>>>(logits);
    }
    // Kernel 2: one block per batch
    topk_kernel<<<B, 256>>>();
    // Kernel 3: one warp per detection
    {
        int dets = B * K;
        int warps_per_block = 8;
        int blocks = (dets + warps_per_block - 1) / warps_per_block;
        gather_kernel<<<blocks, warps_per_block * 32>>>(boxes, logits, out);
    }
    (void)in_sizes; (void)n_in; (void)out_size;
}

// round 3
// speedup vs baseline: 1.6024x; 1.5930x over previous
#include <cuda_runtime.h>
#include <cstdint>

// Problem shape (fixed by the dataset)
#define B 16
#define Q 20000
#define C 80
#define K 100
#define NCHUNK 16
#define CH (Q / NCHUNK)   // 1250 rows per stage-1 chunk

// Scratch (no cudaMalloc allowed). All fully overwritten every call (deterministic).
__device__ unsigned int       g_keys[B * Q];
__device__ unsigned long long g_cand[B * NCHUNK * K];
__device__ int                g_topk[B * K];

// float -> uint monotone map (bigger float => bigger uint)
__device__ __forceinline__ unsigned int f2u(float f) {
    unsigned int u = __float_as_uint(f);
    return (u & 0x80000000u) ? ~u : (u | 0x80000000u);
}

// ---------------------------------------------------------------------------
// Kernel 1: per-row max over C=80 logits.
// 4 threads per row, each loads 5 float4 (20 floats), 2-shuffle reduce.
// ---------------------------------------------------------------------------
__global__ void score_kernel(const float4* __restrict__ lg) {
    int t = blockIdx.x * blockDim.x + threadIdx.x;
    int row = t >> 2;
    int q = t & 3;
    if (row >= B * Q) return;

    const float4* p = lg + row * 20 + q * 5;
    float4 v0 = p[0], v1 = p[1], v2 = p[2], v3 = p[3], v4 = p[4];

    float m;
    m = fmaxf(fmaxf(v0.x, v0.y), fmaxf(v0.z, v0.w));
    m = fmaxf(m, fmaxf(fmaxf(v1.x, v1.y), fmaxf(v1.z, v1.w)));
    m = fmaxf(m, fmaxf(fmaxf(v2.x, v2.y), fmaxf(v2.z, v2.w)));
    m = fmaxf(m, fmaxf(fmaxf(v3.x, v3.y), fmaxf(v3.z, v3.w)));
    m = fmaxf(m, fmaxf(fmaxf(v4.x, v4.y), fmaxf(v4.z, v4.w)));

    m = fmaxf(m, __shfl_xor_sync(0xffffffffu, m, 1));
    m = fmaxf(m, __shfl_xor_sync(0xffffffffu, m, 2));

    if (q == 0) g_keys[row] = f2u(m);
}

// ---------------------------------------------------------------------------
// Kernel 2a: stage-1 top-K. One block per (batch, chunk of 1250 rows).
// Exact radix-select in smem-staged keys, aggregated histogram atomics,
// parallel suffix-scan bin selection, bitonic-256 of (key|~idx) composites.
// Writes the chunk's top-100 composites to g_cand.
// ---------------------------------------------------------------------------
__global__ void topk_stage1() {
    const int b  = blockIdx.x >> 4;
    const int ch = blockIdx.x & 15;
    const int tid = threadIdx.x;   // 256 threads
    const unsigned int* keys = g_keys + b * Q + ch * CH;

    __shared__ unsigned int sk[CH];
    __shared__ int hist[256];
    __shared__ int scan[256];
    __shared__ unsigned int s_prefix;
    __shared__ int s_krem;
    __shared__ int s_cnt;
    __shared__ unsigned long long cand[256];

    for (int i = tid; i < CH; i += 256) sk[i] = keys[i];
    if (tid == 0) { s_prefix = 0u; s_krem = K; s_cnt = 0; }
    __syncthreads();

    // 4 MSB-first radix passes -> exact 100th-largest key
    for (int pass = 0; pass < 4; ++pass) {
        int shift = 24 - 8 * pass;
        unsigned int dmask = pass ? (0xFFFFFFFFu << (shift + 8)) : 0u;
        unsigned int prefix = s_prefix;

        hist[tid] = 0;
        __syncthreads();

        for (int i = tid; i < CH; i += 256) {
            unsigned int kk = sk[i];
            if ((kk & dmask) == prefix) {
                unsigned int d = (kk >> shift) & 255u;
                unsigned int mask = __match_any_sync(__activemask(), d);
                int leader = __ffs(mask) - 1;
                if ((tid & 31) == leader) atomicAdd(&hist[d], __popc(mask));
            }
        }
        __syncthreads();

        // parallel suffix sum: scan[d] = sum_{j>=d} hist[j]
        scan[tid] = hist[tid];
        __syncthreads();
        #pragma unroll
        for (int off = 1; off < 256; off <<= 1) {
            int v = (tid + off < 256) ? scan[tid + off] : 0;
            __syncthreads();
            scan[tid] += v;
            __syncthreads();
        }

        int krem = s_krem;
        int nxt = (tid == 255) ? 0 : scan[tid + 1];
        int cur = scan[tid];
        __syncthreads();                 // all reads of s_krem done before write
        if (cur >= krem && nxt < krem) { // exactly one thread matches
            s_prefix = prefix | ((unsigned int)tid << shift);
            s_krem = krem - nxt;
        }
        __syncthreads();
    }

    unsigned int T = s_prefix;  // exact K-th largest key in this chunk

    // gather candidates >= T (count in [K, K + dups])
    for (int i = tid; i < CH; i += 256) {
        unsigned int kk = sk[i];
        if (kk >= T) {
            int pos = atomicAdd(&s_cnt, 1);
            if (pos < 256) {
                unsigned int gidx = (unsigned int)(ch * CH + i);  // idx within batch
                cand[pos] = ((unsigned long long)kk << 32) |
                            (unsigned long long)(0xFFFFFFFFu - gidx);
            }
        }
    }
    __syncthreads();
    int n = s_cnt < 256 ? s_cnt : 256;
    if (tid >= n) cand[tid] = 0ull;
    __syncthreads();

    // bitonic sort 256 descending (key desc; ties: ~idx desc == idx asc)
    for (int kk = 2; kk <= 256; kk <<= 1) {
        for (int j = kk >> 1; j > 0; j >>= 1) {
            int i = tid, ixj = i ^ j;
            if (ixj > i) {
                unsigned long long a = cand[i], bb = cand[ixj];
                bool up = ((i & kk) == 0);
                if ((a < bb) == up) { cand[i] = bb; cand[ixj] = a; }
            }
            __syncthreads();
        }
    }

    if (tid < K) g_cand[(b * NCHUNK + ch) * K + tid] = cand[tid];
}

// ---------------------------------------------------------------------------
// Kernel 2b: stage-2. One block per batch, 1024 threads.
// Bitonic-2048 over the 16*100 = 1600 stage-1 winners -> global top-100.
// ---------------------------------------------------------------------------
__global__ void topk_stage2() {
    const int b = blockIdx.x;
    const int tid = threadIdx.x;   // 1024 threads
    __shared__ unsigned long long s[2048];

    const unsigned long long* src = g_cand + b * NCHUNK * K;  // 1600 entries
    s[tid]        = (tid        < NCHUNK * K) ? src[tid]        : 0ull;
    s[tid + 1024] = (tid + 1024 < NCHUNK * K) ? src[tid + 1024] : 0ull;
    __syncthreads();

    for (int kk = 2; kk <= 2048; kk <<= 1) {
        for (int j = kk >> 1; j > 0; j >>= 1) {
            #pragma unroll
            for (int eo = 0; eo < 2048; eo += 1024) {
                int e = tid + eo;
                int p = e ^ j;
                if (p > e) {
                    unsigned long long a = s[e], bb = s[p];
                    bool up = ((e & kk) == 0);
                    if ((a < bb) == up) { s[e] = bb; s[p] = a; }
                }
            }
            __syncthreads();
        }
    }

    if (tid < K) {
        unsigned int enc = (unsigned int)(s[tid] & 0xFFFFFFFFull);
        g_topk[b * K + tid] = (int)(0xFFFFFFFFu - enc);
    }
}

// ---------------------------------------------------------------------------
// Kernel 3: gather boxes + sigmoid(logits). One warp per detection.
// Output layout: [B*K*4 boxes][B*K*C scores], both f32.
// ---------------------------------------------------------------------------
__global__ void gather_kernel(const float* __restrict__ boxes,
                              const float* __restrict__ logits,
                              float* __restrict__ out) {
    int warp_id = (blockIdx.x * blockDim.x + threadIdx.x) >> 5;
    int lane = threadIdx.x & 31;
    if (warp_id >= B * K) return;

    int b = warp_id / K;
    int idx = g_topk[warp_id];

    const float* lrow = logits + ((long long)b * Q + idx) * C;
    float* srow = out + (long long)B * K * 4 + (long long)warp_id * C;

    float x0 = lrow[lane];
    float x1 = lrow[lane + 32];
    srow[lane]      = 1.f / (1.f + __expf(-x0));
    srow[lane + 32] = 1.f / (1.f + __expf(-x1));
    if (lane < 16) {
        float x2 = lrow[lane + 64];
        srow[lane + 64] = 1.f / (1.f + __expf(-x2));
    }

    if (lane < 4) {
        out[(long long)warp_id * 4 + lane] = boxes[((long long)b * Q + idx) * 4 + lane];
    }
}

// ---------------------------------------------------------------------------
extern "C" void kernel_launch(void* const* d_in, const int* in_sizes, int n_in,
                              void* d_out, int out_size) {
    const float* boxes  = (const float*)d_in[0];   // (B,Q,4)
    const float* logits = (const float*)d_in[1];   // (B,Q,C)
    float* out = (float*)d_out;

    // Kernel 1: 4 threads per row
    {
        int threads = B * Q * 4;
        int blocks = (threads + 255) / 256;
        score_kernel<<<blocks, 256>>>((const float4*)logits);
    }
    // Kernel 2a: 16 chunks per batch
    topk_stage1<<<B * NCHUNK, 256>>>();
    // Kernel 2b: one block per batch
    topk_stage2<<<B, 1024>>>();
    // Kernel 3: one warp per detection
    {
        int dets = B * K;
        int blocks = (dets * 32 + 255) / 256;
        gather_kernel<<<blocks, 256>>>(boxes, logits, out);
    }
    (void)in_sizes; (void)n_in; (void)out_size;
}